// round 3
// baseline (speedup 1.0000x reference)
#include <cuda_runtime.h>
#include <cstdint>

// Shapes (fixed by the problem)
#define B_DIM 16
#define N_NODES 1024
#define C_DIM 64
#define O_DIM 64
#define D_DIM 10
#define K_TERMS 5          // 1 + 2*CHEB_K
#define KC (K_TERMS * C_DIM)   // 320

// Scratch (allocation-free rule: __device__ globals)
// g_hop slabs: slab = 2*s + h  -> 0=s0h1, 1=s0h2, 2=s1h1, 3=s1h2 ; layout [slab][b][n][c]
__device__ float g_hop[(size_t)4 * B_DIM * N_NODES * C_DIM];     // 16.8 MB
// g_W: per-node hypernet weights [n][k][c][o] = [1024][5][64][64]
__device__ float g_W[(size_t)N_NODES * K_TERMS * C_DIM * O_DIM]; // 83.9 MB

// ---------------------------------------------------------------------------
// Hop GEMM: Y[1024,64] = A[1024,1024] @ X[1024,64] for 32 (support,batch) pairs.
// BM=64, BN=64, BK=32, 128 threads, per-thread 8x4 outputs held as 4x4 packed
// f32x2 accumulators (row pairs). fma.rn.f32x2 doubles fp32 FMA throughput.
// ---------------------------------------------------------------------------
__global__ __launch_bounds__(128) void hop_gemm(const float* __restrict__ adj,
                                                const float* __restrict__ xin,
                                                int h) {
    constexpr int BM = 64, BN = 64, BK = 32;
    __shared__ float As[BK][BM + 4];  // transposed A tile; row stride 68 floats (16B aligned)
    __shared__ float Xs[BK][BN];

    const int z = blockIdx.y;            // 0..31 -> s*16+b
    const int s = z >> 4;
    const int b = z & 15;

    const float* A = adj + (size_t)z * (N_NODES * N_NODES);
    const float* X = (h == 0)
        ? (xin + (size_t)b * (N_NODES * C_DIM))
        : (g_hop + ((size_t)(2 * s) * B_DIM + b) * (N_NODES * C_DIM));
    float* Y = g_hop + ((size_t)(2 * s + h) * B_DIM + b) * (N_NODES * C_DIM);

    const int m0  = blockIdx.x * BM;
    const int tid = threadIdx.x;
    const int tr  = tid >> 4;    // 0..7  (8 thread-rows, 8 output rows each)
    const int tc  = tid & 15;    // 0..15 (16 thread-cols, 4 output cols each)

    // Global-load index decomposition (constant across i because 128 % 16 == 0)
    const int ar  = tid >> 3;          // A tile row base (0..15), +16 per i
    const int akc = (tid & 7) << 2;    // A tile k base (0,4,...,28)
    const int xr  = tid >> 4;          // X tile row base (0..7), +8 per i
    const int xc  = (tid & 15) << 2;   // X tile col (0,4,...,60)

    unsigned long long acc[4][4];
    #pragma unroll
    for (int i = 0; i < 4; i++)
        #pragma unroll
        for (int j = 0; j < 4; j++) acc[i][j] = 0ull;

    float4 a_reg[4], x_reg[4];

    // Preload k-tile 0 into registers
    #pragma unroll
    for (int i = 0; i < 4; i++) {
        a_reg[i] = *(const float4*)&A[(size_t)(m0 + ar + i * 16) * N_NODES + akc];
        x_reg[i] = *(const float4*)&X[(size_t)(xr + i * 8) * C_DIM + xc];
    }

    const int NT = N_NODES / BK;  // 32
    for (int kt = 0; kt < NT; ++kt) {
        // Commit staged registers to SMEM (A transposed)
        #pragma unroll
        for (int i = 0; i < 4; i++) {
            const int r = ar + i * 16;
            As[akc + 0][r] = a_reg[i].x;
            As[akc + 1][r] = a_reg[i].y;
            As[akc + 2][r] = a_reg[i].z;
            As[akc + 3][r] = a_reg[i].w;
            *(float4*)&Xs[xr + i * 8][xc] = x_reg[i];
        }
        __syncthreads();

        // Prefetch next k-tile
        if (kt + 1 < NT) {
            const int k0 = (kt + 1) * BK;
            #pragma unroll
            for (int i = 0; i < 4; i++) {
                a_reg[i] = *(const float4*)&A[(size_t)(m0 + ar + i * 16) * N_NODES + k0 + akc];
                x_reg[i] = *(const float4*)&X[(size_t)(k0 + xr + i * 8) * C_DIM + xc];
            }
        }

        #pragma unroll 8
        for (int k = 0; k < BK; k++) {
            // 8 A rows as 4 naturally-packed f32x2 pairs (consecutive rows in As)
            const ulonglong2 av0 = *(const ulonglong2*)&As[k][tr * 8];
            const ulonglong2 av1 = *(const ulonglong2*)&As[k][tr * 8 + 4];
            const unsigned long long ap[4] = {av0.x, av0.y, av1.x, av1.y};

            const float4 xf = *(const float4*)&Xs[k][tc * 4];
            unsigned long long xp[4];
            asm("mov.b64 %0, {%1, %1};" : "=l"(xp[0]) : "f"(xf.x));
            asm("mov.b64 %0, {%1, %1};" : "=l"(xp[1]) : "f"(xf.y));
            asm("mov.b64 %0, {%1, %1};" : "=l"(xp[2]) : "f"(xf.z));
            asm("mov.b64 %0, {%1, %1};" : "=l"(xp[3]) : "f"(xf.w));

            #pragma unroll
            for (int r2 = 0; r2 < 4; r2++)
                #pragma unroll
                for (int c = 0; c < 4; c++)
                    asm("fma.rn.f32x2 %0, %1, %2, %0;"
                        : "+l"(acc[r2][c]) : "l"(ap[r2]), "l"(xp[c]));
        }
        __syncthreads();
    }

    // Epilogue: unpack row-pairs and store two coalesced float4 rows per pair
    #pragma unroll
    for (int r2 = 0; r2 < 4; r2++) {
        float lo0, hi0, lo1, hi1, lo2, hi2, lo3, hi3;
        asm("mov.b64 {%0, %1}, %2;" : "=f"(lo0), "=f"(hi0) : "l"(acc[r2][0]));
        asm("mov.b64 {%0, %1}, %2;" : "=f"(lo1), "=f"(hi1) : "l"(acc[r2][1]));
        asm("mov.b64 {%0, %1}, %2;" : "=f"(lo2), "=f"(hi2) : "l"(acc[r2][2]));
        asm("mov.b64 {%0, %1}, %2;" : "=f"(lo3), "=f"(hi3) : "l"(acc[r2][3]));
        const int row = m0 + tr * 8 + r2 * 2;
        *(float4*)&Y[(size_t)row * C_DIM + tc * 4]       = make_float4(lo0, lo1, lo2, lo3);
        *(float4*)&Y[(size_t)(row + 1) * C_DIM + tc * 4] = make_float4(hi0, hi1, hi2, hi3);
    }
}

// ---------------------------------------------------------------------------
// W[n,k,c,o] = sum_d emb[n,d] * wpool[d,k,c,o]   (wpool stays hot in L2)
// ---------------------------------------------------------------------------
__global__ __launch_bounds__(256) void compute_W(const float* __restrict__ emb,
                                                 const float* __restrict__ wpool) {
    const int n = blockIdx.x;
    float e[D_DIM];
    #pragma unroll
    for (int d = 0; d < D_DIM; d++) e[d] = emb[n * D_DIM + d];

    float* Wn = g_W + (size_t)n * (KC * O_DIM);  // 20480 floats
    for (int j = threadIdx.x * 4; j < KC * O_DIM; j += 256 * 4) {
        float4 acc = make_float4(0.f, 0.f, 0.f, 0.f);
        #pragma unroll
        for (int d = 0; d < D_DIM; d++) {
            const float4 w = *(const float4*)&wpool[(size_t)d * (KC * O_DIM) + j];
            acc.x = fmaf(e[d], w.x, acc.x);
            acc.y = fmaf(e[d], w.y, acc.y);
            acc.z = fmaf(e[d], w.z, acc.z);
            acc.w = fmaf(e[d], w.w, acc.w);
        }
        *(float4*)&Wn[j] = acc;
    }
}

// ---------------------------------------------------------------------------
// out[b,n,o] = sum_{kc} x_g[b,n,kc] * W[n,kc,o] + (emb[n] @ bias_pool)[o]
// One CTA per node n; x_g for all 16 batches staged in SMEM; W[n] streamed once.
// ---------------------------------------------------------------------------
__global__ __launch_bounds__(256) void final_contract(const float* __restrict__ xin,
                                                      const float* __restrict__ emb,
                                                      const float* __restrict__ bpool,
                                                      float* __restrict__ out) {
    __shared__ float xg[B_DIM][KC];  // 16 x 320 floats = 20 KB
    const int n   = blockIdx.x;
    const int tid = threadIdx.x;

    // Stage x_g: k=0 is x itself, k>=1 from hop slab (k-1)
    #pragma unroll
    for (int i = 0; i < 5; i++) {
        const int id  = tid + i * 256;   // 0..1279 float4 slots
        const int b   = id / 80;
        const int rem = id % 80;
        const int k   = rem >> 4;        // 0..4
        const int c4  = (rem & 15) << 2;
        const float* src = (k == 0)
            ? &xin[((size_t)b * N_NODES + n) * C_DIM + c4]
            : &g_hop[(((size_t)(k - 1) * B_DIM + b) * N_NODES + n) * C_DIM + c4];
        *(float4*)&xg[b][k * C_DIM + c4] = *(const float4*)src;
    }
    __syncthreads();

    const int o = tid & 63;
    const int g = tid >> 6;  // batch group: handles b = g, g+4, g+8, g+12

    float bias = 0.f;
    #pragma unroll
    for (int d = 0; d < D_DIM; d++)
        bias = fmaf(emb[n * D_DIM + d], bpool[d * O_DIM + o], bias);

    float acc0 = bias, acc1 = bias, acc2 = bias, acc3 = bias;
    const float* Wn = g_W + (size_t)n * (KC * O_DIM);

    for (int kc = 0; kc < KC; kc += 4) {
        const float4 x0 = *(const float4*)&xg[g][kc];
        const float4 x1 = *(const float4*)&xg[g + 4][kc];
        const float4 x2 = *(const float4*)&xg[g + 8][kc];
        const float4 x3 = *(const float4*)&xg[g + 12][kc];
        const float* xp0 = (const float*)&x0;
        const float* xp1 = (const float*)&x1;
        const float* xp2 = (const float*)&x2;
        const float* xp3 = (const float*)&x3;
        #pragma unroll
        for (int j = 0; j < 4; j++) {
            const float w = Wn[(kc + j) * O_DIM + o];  // coalesced across o
            acc0 = fmaf(xp0[j], w, acc0);
            acc1 = fmaf(xp1[j], w, acc1);
            acc2 = fmaf(xp2[j], w, acc2);
            acc3 = fmaf(xp3[j], w, acc3);
        }
    }

    out[((size_t)(g     ) * N_NODES + n) * O_DIM + o] = acc0;
    out[((size_t)(g +  4) * N_NODES + n) * O_DIM + o] = acc1;
    out[((size_t)(g +  8) * N_NODES + n) * O_DIM + o] = acc2;
    out[((size_t)(g + 12) * N_NODES + n) * O_DIM + o] = acc3;
}

// ---------------------------------------------------------------------------
extern "C" void kernel_launch(void* const* d_in, const int* in_sizes, int n_in,
                              void* d_out, int out_size) {
    const float* x     = (const float*)d_in[0];  // [16,1024,64]
    const float* adj   = (const float*)d_in[1];  // [2,16,1024,1024]
    const float* emb   = (const float*)d_in[2];  // [1024,10]
    const float* wpool = (const float*)d_in[3];  // [10,5,64,64]
    const float* bpool = (const float*)d_in[4];  // [10,64]
    float* out = (float*)d_out;                  // [16,1024,64]

    const dim3 ggemm(N_NODES / 64, 32, 1);       // 16 row-tiles x 32 matrices
    hop_gemm<<<ggemm, 128>>>(adj, x, 0);         // hop1 for both supports
    hop_gemm<<<ggemm, 128>>>(adj, x, 1);         // hop2 (depends on hop1)
    compute_W<<<N_NODES, 256>>>(emb, wpool);     // independent of hops
    final_contract<<<N_NODES, 256>>>(x, emb, bpool, out);
}

// round 7
// speedup vs baseline: 1.0064x; 1.0064x over previous
#include <cuda_runtime.h>
#include <cuda_bf16.h>
#include <cstdint>

// Shapes (fixed by the problem)
#define B_DIM 16
#define N_NODES 1024
#define C_DIM 64
#define O_DIM 64
#define D_DIM 10
#define K_TERMS 5              // 1 + 2*CHEB_K
#define KC (K_TERMS * C_DIM)   // 320

// Scratch (allocation-free rule: __device__ globals)
// g_hop slabs: 0=s0h1, 1=s0h2, 2=s1h1, 3=s1h2 ; layout [slab][b][n][c], fp32
__device__ float g_hop[(size_t)4 * B_DIM * N_NODES * C_DIM];     // 16.8 MB
__device__ float g_W[(size_t)N_NODES * KC * O_DIM];              // 83.9 MB

// ---------------------------------------------------------------------------
// Helpers
// ---------------------------------------------------------------------------
__device__ __forceinline__ uint32_t smem_u32(const void* p) {
    uint32_t a;
    asm("{ .reg .u64 t; cvta.to.shared.u64 t, %1; cvt.u32.u64 %0, t; }" : "=r"(a) : "l"(p));
    return a;
}

// hi/lo bf16 split of two fp32 values, packed bf16x2 (low half = first elem)
__device__ __forceinline__ void split2(float v0, float v1, uint32_t& hi, uint32_t& lo) {
    asm("cvt.rn.bf16x2.f32 %0, %1, %2;" : "=r"(hi) : "f"(v1), "f"(v0));
    float r0 = v0 - __uint_as_float(hi << 16);
    float r1 = v1 - __uint_as_float(hi & 0xFFFF0000u);
    asm("cvt.rn.bf16x2.f32 %0, %1, %2;" : "=r"(lo) : "f"(r1), "f"(r0));
}

__device__ __forceinline__ void ldmatrix_x4(uint32_t* r, uint32_t addr) {
    asm volatile("ldmatrix.sync.aligned.m8n8.x4.shared.b16 {%0,%1,%2,%3}, [%4];"
                 : "=r"(r[0]), "=r"(r[1]), "=r"(r[2]), "=r"(r[3]) : "r"(addr));
}

__device__ __forceinline__ void mma_bf16(float* c, const uint32_t* a, const uint32_t* b) {
    asm volatile(
        "mma.sync.aligned.m16n8k16.row.col.f32.bf16.bf16.f32 "
        "{%0,%1,%2,%3}, {%4,%5,%6,%7}, {%8,%9}, {%0,%1,%2,%3};"
        : "+f"(c[0]), "+f"(c[1]), "+f"(c[2]), "+f"(c[3])
        : "r"(a[0]), "r"(a[1]), "r"(a[2]), "r"(a[3]), "r"(b[0]), "r"(b[1]));
}

// ---------------------------------------------------------------------------
// Hop GEMM via warp-level bf16 mma.sync (legacy HMMA path; tcgen05 is
// ptxas-gated to sm_103a which this harness does not target).
// Y[1024,64] = A[1024,1024] @ X[1024,64] for 32 (support,batch) matrices.
// fp32 accuracy via bf16 hi/lo split: Ah*Xh + Al*Xh + Ah*Xl.
// CTA: 256 thr / 8 warps, tile M=128 N=64, BK=32, double-buffered SMEM.
// ---------------------------------------------------------------------------
#define HOP_BK 32
#define HOP_NCHUNK (N_NODES / HOP_BK)   // 32
#define AS_STRIDE 40                    // bf16/row (80B: 16B-aligned, ldmatrix conflict-free)
#define XS_STRIDE 34                    // bf16/row (68B: odd bank stride, STS conflict-free)
#define AS_BYTES (128 * AS_STRIDE * 2)  // 10240
#define XS_BYTES (64 * XS_STRIDE * 2)   // 4352
#define OFF_AH 0
#define OFF_AL AS_BYTES
#define OFF_XH (2 * AS_BYTES)
#define OFF_XL (2 * AS_BYTES + XS_BYTES)
#define BUF_BYTES (2 * AS_BYTES + 2 * XS_BYTES)  // 29184
#define HOP_SMEM (2 * BUF_BYTES)                 // 58368

struct Stage {
    float4 a[4];
    float  xv[8];
};

__device__ __forceinline__ void ldg_chunk(Stage& st, const float* __restrict__ A,
                                          const float* __restrict__ X,
                                          int m0, int k0, int tid) {
    #pragma unroll
    for (int q = 0; q < 4; q++) {
        const int f = tid + 256 * q;          // float4 slot 0..1023
        const int m = f >> 3, kq = f & 7;     // 8 float4 per 32-wide row
        st.a[q] = *(const float4*)(A + (size_t)(m0 + m) * N_NODES + k0 + kq * 4);
    }
    const int n = tid & 63, k8 = (tid >> 6) * 8;
    #pragma unroll
    for (int j = 0; j < 8; j++)
        st.xv[j] = X[(size_t)(k0 + k8 + j) * C_DIM + n];   // coalesced along n
}

__device__ __forceinline__ void sts_chunk(const Stage& st, char* buf, int tid) {
    #pragma unroll
    for (int q = 0; q < 4; q++) {
        const int f = tid + 256 * q;
        const int m = f >> 3, kq = f & 7;
        uint32_t h0, l0, h1, l1;
        split2(st.a[q].x, st.a[q].y, h0, l0);
        split2(st.a[q].z, st.a[q].w, h1, l1);
        const uint32_t off = (uint32_t)m * (AS_STRIDE * 2) + kq * 8;
        *(uint2*)(buf + OFF_AH + off) = make_uint2(h0, h1);
        *(uint2*)(buf + OFF_AL + off) = make_uint2(l0, l1);
    }
    const int n = tid & 63, k8 = (tid >> 6) * 8;
    #pragma unroll
    for (int j = 0; j < 8; j += 2) {
        uint32_t h, l;
        split2(st.xv[j], st.xv[j + 1], h, l);     // pack {k, k+1}
        const uint32_t off = (uint32_t)n * (XS_STRIDE * 2) + (k8 + j) * 2;
        *(uint32_t*)(buf + OFF_XH + off) = h;
        *(uint32_t*)(buf + OFF_XL + off) = l;
    }
}

__device__ __forceinline__ void compute_chunk(float acc[2][4][4], const char* bufp,
                                              uint32_t bufa, int warp_m, int warp_n,
                                              int lane) {
    #pragma unroll
    for (int k16 = 0; k16 < 2; k16++) {
        const int k0 = k16 * 16;
        uint32_t ah[2][4], al[2][4];
        #pragma unroll
        for (int mi = 0; mi < 2; mi++) {
            const uint32_t row = warp_m + mi * 16 + (lane & 15);
            const uint32_t addr = bufa + OFF_AH + row * (AS_STRIDE * 2)
                                + (k0 + (lane >> 4) * 8) * 2;
            ldmatrix_x4(ah[mi], addr);
            ldmatrix_x4(al[mi], addr + (OFF_AL - OFF_AH));
        }
        uint32_t bh[4][2], bl[4][2];
        #pragma unroll
        for (int nf = 0; nf < 4; nf++) {
            const int n = warp_n + nf * 8 + (lane >> 2);
            const uint32_t boff = (uint32_t)n * (XS_STRIDE * 2) + (k0 + 2 * (lane & 3)) * 2;
            bh[nf][0] = *(const uint32_t*)(bufp + OFF_XH + boff);        // k, k+1
            bh[nf][1] = *(const uint32_t*)(bufp + OFF_XH + boff + 16);   // k+8, k+9
            bl[nf][0] = *(const uint32_t*)(bufp + OFF_XL + boff);
            bl[nf][1] = *(const uint32_t*)(bufp + OFF_XL + boff + 16);
        }
        #pragma unroll
        for (int mi = 0; mi < 2; mi++)
            #pragma unroll
            for (int nf = 0; nf < 4; nf++) {
                mma_bf16(acc[mi][nf], ah[mi], bh[nf]);
                mma_bf16(acc[mi][nf], al[mi], bh[nf]);
                mma_bf16(acc[mi][nf], ah[mi], bl[nf]);
            }
    }
}

__global__ __launch_bounds__(256) void hop_gemm_mma(const float* __restrict__ adj,
                                                    const float* __restrict__ xin,
                                                    int h) {
    extern __shared__ char smem[];
    const uint32_t smem_base = smem_u32(smem);
    const int tid = threadIdx.x;
    const int lane = tid & 31;
    const int wid = tid >> 5;
    const int warp_m = (wid & 3) * 32;    // 4 warps over M
    const int warp_n = (wid >> 2) * 32;   // 2 warps over N

    const int z = blockIdx.y;             // s*16 + b
    const int s = z >> 4;
    const int b = z & 15;
    const int m0 = blockIdx.x * 128;

    const float* A = adj + (size_t)z * (N_NODES * N_NODES);
    const float* X = (h == 0)
        ? (xin + (size_t)b * (N_NODES * C_DIM))
        : (g_hop + ((size_t)(2 * s) * B_DIM + b) * (N_NODES * C_DIM));
    float* Y = g_hop + ((size_t)(2 * s + h) * B_DIM + b) * (N_NODES * C_DIM);

    float acc[2][4][4];
    #pragma unroll
    for (int mi = 0; mi < 2; mi++)
        #pragma unroll
        for (int nf = 0; nf < 4; nf++)
            #pragma unroll
            for (int e = 0; e < 4; e++) acc[mi][nf][e] = 0.f;

    Stage st;
    ldg_chunk(st, A, X, m0, 0, tid);
    sts_chunk(st, smem, tid);
    __syncthreads();

    for (int kt = 0; kt < HOP_NCHUNK; kt++) {
        const int bf = kt & 1;
        if (kt + 1 < HOP_NCHUNK)
            ldg_chunk(st, A, X, m0, (kt + 1) * HOP_BK, tid);   // overlap with MMA
        compute_chunk(acc, smem + bf * BUF_BYTES, smem_base + bf * BUF_BYTES,
                      warp_m, warp_n, lane);
        __syncthreads();
        if (kt + 1 < HOP_NCHUNK)
            sts_chunk(st, smem + ((kt + 1) & 1) * BUF_BYTES, tid);
        __syncthreads();
    }

    // Epilogue: c-frag -> Y  (c0,c1: row=lane/4, cols 2*(lane%4)+{0,1}; c2,c3: row+8)
    const int r_base = m0 + warp_m + (lane >> 2);
    const int c_base = warp_n + 2 * (lane & 3);
    #pragma unroll
    for (int mi = 0; mi < 2; mi++)
        #pragma unroll
        for (int nf = 0; nf < 4; nf++) {
            const int row = r_base + mi * 16;
            const int col = c_base + nf * 8;
            *(float2*)(Y + (size_t)row * C_DIM + col) =
                make_float2(acc[mi][nf][0], acc[mi][nf][1]);
            *(float2*)(Y + (size_t)(row + 8) * C_DIM + col) =
                make_float2(acc[mi][nf][2], acc[mi][nf][3]);
        }
}

// ---------------------------------------------------------------------------
// W[n,k,c,o] = sum_d emb[n,d] * wpool[d,k,c,o]   (wpool stays hot in L2)
// ---------------------------------------------------------------------------
__global__ __launch_bounds__(256) void compute_W(const float* __restrict__ emb,
                                                 const float* __restrict__ wpool) {
    const int n = blockIdx.x;
    float e[D_DIM];
    #pragma unroll
    for (int d = 0; d < D_DIM; d++) e[d] = emb[n * D_DIM + d];

    float* Wn = g_W + (size_t)n * (KC * O_DIM);
    for (int j = threadIdx.x * 4; j < KC * O_DIM; j += 256 * 4) {
        float4 acc = make_float4(0.f, 0.f, 0.f, 0.f);
        #pragma unroll
        for (int d = 0; d < D_DIM; d++) {
            const float4 w = *(const float4*)&wpool[(size_t)d * (KC * O_DIM) + j];
            acc.x = fmaf(e[d], w.x, acc.x);
            acc.y = fmaf(e[d], w.y, acc.y);
            acc.z = fmaf(e[d], w.z, acc.z);
            acc.w = fmaf(e[d], w.w, acc.w);
        }
        *(float4*)&Wn[j] = acc;
    }
}

// ---------------------------------------------------------------------------
// out[b,n,o] = sum_{kc} x_g[b,n,kc] * W[n,kc,o] + (emb[n] @ bias_pool)[o]
// ---------------------------------------------------------------------------
__global__ __launch_bounds__(256) void final_contract(const float* __restrict__ xin,
                                                      const float* __restrict__ emb,
                                                      const float* __restrict__ bpool,
                                                      float* __restrict__ out) {
    __shared__ float xg[B_DIM][KC];
    const int n   = blockIdx.x;
    const int tid = threadIdx.x;

    #pragma unroll
    for (int i = 0; i < 5; i++) {
        const int id  = tid + i * 256;
        const int b   = id / 80;
        const int rem = id % 80;
        const int k   = rem >> 4;
        const int c4  = (rem & 15) << 2;
        const float* src = (k == 0)
            ? &xin[((size_t)b * N_NODES + n) * C_DIM + c4]
            : &g_hop[(((size_t)(k - 1) * B_DIM + b) * N_NODES + n) * C_DIM + c4];
        *(float4*)&xg[b][k * C_DIM + c4] = *(const float4*)src;
    }
    __syncthreads();

    const int o = tid & 63;
    const int g = tid >> 6;

    float bias = 0.f;
    #pragma unroll
    for (int d = 0; d < D_DIM; d++)
        bias = fmaf(emb[n * D_DIM + d], bpool[d * O_DIM + o], bias);

    float acc0 = bias, acc1 = bias, acc2 = bias, acc3 = bias;
    const float* Wn = g_W + (size_t)n * (KC * O_DIM);

    for (int kc = 0; kc < KC; kc += 4) {
        const float4 x0 = *(const float4*)&xg[g][kc];
        const float4 x1 = *(const float4*)&xg[g + 4][kc];
        const float4 x2 = *(const float4*)&xg[g + 8][kc];
        const float4 x3 = *(const float4*)&xg[g + 12][kc];
        const float* xp0 = (const float*)&x0;
        const float* xp1 = (const float*)&x1;
        const float* xp2 = (const float*)&x2;
        const float* xp3 = (const float*)&x3;
        #pragma unroll
        for (int j = 0; j < 4; j++) {
            const float w = Wn[(kc + j) * O_DIM + o];
            acc0 = fmaf(xp0[j], w, acc0);
            acc1 = fmaf(xp1[j], w, acc1);
            acc2 = fmaf(xp2[j], w, acc2);
            acc3 = fmaf(xp3[j], w, acc3);
        }
    }

    out[((size_t)(g     ) * N_NODES + n) * O_DIM + o] = acc0;
    out[((size_t)(g +  4) * N_NODES + n) * O_DIM + o] = acc1;
    out[((size_t)(g +  8) * N_NODES + n) * O_DIM + o] = acc2;
    out[((size_t)(g + 12) * N_NODES + n) * O_DIM + o] = acc3;
}

// ---------------------------------------------------------------------------
extern "C" void kernel_launch(void* const* d_in, const int* in_sizes, int n_in,
                              void* d_out, int out_size) {
    const float* x     = (const float*)d_in[0];  // [16,1024,64]
    const float* adj   = (const float*)d_in[1];  // [2,16,1024,1024]
    const float* emb   = (const float*)d_in[2];  // [1024,10]
    const float* wpool = (const float*)d_in[3];  // [10,5,64,64]
    const float* bpool = (const float*)d_in[4];  // [10,64]
    float* out = (float*)d_out;                  // [16,1024,64]

    static int smem_set = 0;
    if (!smem_set) {
        cudaFuncSetAttribute(hop_gemm_mma, cudaFuncAttributeMaxDynamicSharedMemorySize,
                             HOP_SMEM);
        smem_set = 1;
    }

    const dim3 ggemm(N_NODES / 128, 32, 1);               // 8 M-tiles x 32 matrices
    hop_gemm_mma<<<ggemm, 256, HOP_SMEM>>>(adj, x, 0);    // hop1 (both supports)
    hop_gemm_mma<<<ggemm, 256, HOP_SMEM>>>(adj, x, 1);    // hop2 (reads hop1)
    compute_W<<<N_NODES, 256>>>(emb, wpool);
    final_contract<<<N_NODES, 256>>>(x, emb, bpool, out);
}

// round 10
// speedup vs baseline: 1.1069x; 1.0999x over previous
#include <cuda_runtime.h>
#include <cuda_bf16.h>
#include <cstdint>

// Shapes (fixed by the problem)
#define B_DIM 16
#define N_NODES 1024
#define C_DIM 64
#define O_DIM 64
#define D_DIM 10
#define K_TERMS 5              // 1 + 2*CHEB_K
#define KC (K_TERMS * C_DIM)   // 320

// Scratch (allocation-free rule: __device__ globals)
// g_hop slabs: 0=s0h1, 1=s0h2, 2=s1h1, 3=s1h2 ; layout [slab][b][n][c], fp32
__device__ float g_hop[(size_t)4 * B_DIM * N_NODES * C_DIM];     // 16.8 MB

// ---------------------------------------------------------------------------
// Helpers
// ---------------------------------------------------------------------------
__device__ __forceinline__ uint32_t smem_u32(const void* p) {
    uint32_t a;
    asm("{ .reg .u64 t; cvta.to.shared.u64 t, %1; cvt.u32.u64 %0, t; }" : "=r"(a) : "l"(p));
    return a;
}

// hi/lo bf16 split of two fp32 values, packed bf16x2 (low half = first elem)
__device__ __forceinline__ void split2(float v0, float v1, uint32_t& hi, uint32_t& lo) {
    asm("cvt.rn.bf16x2.f32 %0, %1, %2;" : "=r"(hi) : "f"(v1), "f"(v0));
    float r0 = v0 - __uint_as_float(hi << 16);
    float r1 = v1 - __uint_as_float(hi & 0xFFFF0000u);
    asm("cvt.rn.bf16x2.f32 %0, %1, %2;" : "=r"(lo) : "f"(r1), "f"(r0));
}

__device__ __forceinline__ void ldmatrix_x4(uint32_t* r, uint32_t addr) {
    asm volatile("ldmatrix.sync.aligned.m8n8.x4.shared.b16 {%0,%1,%2,%3}, [%4];"
                 : "=r"(r[0]), "=r"(r[1]), "=r"(r[2]), "=r"(r[3]) : "r"(addr));
}

__device__ __forceinline__ void mma_bf16(float* c, const uint32_t* a, const uint32_t* b) {
    asm volatile(
        "mma.sync.aligned.m16n8k16.row.col.f32.bf16.bf16.f32 "
        "{%0,%1,%2,%3}, {%4,%5,%6,%7}, {%8,%9}, {%0,%1,%2,%3};"
        : "+f"(c[0]), "+f"(c[1]), "+f"(c[2]), "+f"(c[3])
        : "r"(a[0]), "r"(a[1]), "r"(a[2]), "r"(a[3]), "r"(b[0]), "r"(b[1]));
}

// ---------------------------------------------------------------------------
// Hop GEMM via warp-level bf16 mma.sync (legacy HMMA path; tcgen05 is
// ptxas-gated to sm_103a which this harness does not target).
// Y[1024,64] = A[1024,1024] @ X[1024,64] for 32 (support,batch) matrices.
// fp32 accuracy via bf16 hi/lo split: Ah*Xh + Al*Xh + Ah*Xl.
// CTA: 256 thr / 8 warps, tile M=128 N=64, BK=32, double-buffered SMEM.
// B fragments loaded with scalar LDS (4B-aligned; ldmatrix needs 16B-aligned
// rows which the 68B X stride does not provide — caused R7's misaligned trap).
// ---------------------------------------------------------------------------
#define HOP_BK 32
#define HOP_NCHUNK (N_NODES / HOP_BK)   // 32
#define AS_STRIDE 40                    // bf16/row (80B: 16B-aligned, ldmatrix conflict-free)
#define XS_STRIDE 34                    // bf16/row (68B: odd bank stride, STS conflict-free)
#define AS_BYTES (128 * AS_STRIDE * 2)  // 10240
#define XS_BYTES (64 * XS_STRIDE * 2)   // 4352
#define OFF_AH 0
#define OFF_AL AS_BYTES
#define OFF_XH (2 * AS_BYTES)
#define OFF_XL (2 * AS_BYTES + XS_BYTES)
#define BUF_BYTES (2 * AS_BYTES + 2 * XS_BYTES)  // 29184
#define HOP_SMEM (2 * BUF_BYTES)                 // 58368

struct Stage {
    float4 a[4];
    float  xv[8];
};

__device__ __forceinline__ void ldg_chunk(Stage& st, const float* __restrict__ A,
                                          const float* __restrict__ X,
                                          int m0, int k0, int tid) {
    #pragma unroll
    for (int q = 0; q < 4; q++) {
        const int f = tid + 256 * q;          // float4 slot 0..1023
        const int m = f >> 3, kq = f & 7;     // 8 float4 per 32-wide row
        st.a[q] = *(const float4*)(A + (size_t)(m0 + m) * N_NODES + k0 + kq * 4);
    }
    const int n = tid & 63, k8 = (tid >> 6) * 8;
    #pragma unroll
    for (int j = 0; j < 8; j++)
        st.xv[j] = X[(size_t)(k0 + k8 + j) * C_DIM + n];   // coalesced along n
}

__device__ __forceinline__ void sts_chunk(const Stage& st, char* buf, int tid) {
    #pragma unroll
    for (int q = 0; q < 4; q++) {
        const int f = tid + 256 * q;
        const int m = f >> 3, kq = f & 7;
        uint32_t h0, l0, h1, l1;
        split2(st.a[q].x, st.a[q].y, h0, l0);
        split2(st.a[q].z, st.a[q].w, h1, l1);
        const uint32_t off = (uint32_t)m * (AS_STRIDE * 2) + kq * 8;
        *(uint2*)(buf + OFF_AH + off) = make_uint2(h0, h1);
        *(uint2*)(buf + OFF_AL + off) = make_uint2(l0, l1);
    }
    const int n = tid & 63, k8 = (tid >> 6) * 8;
    #pragma unroll
    for (int j = 0; j < 8; j += 2) {
        uint32_t h, l;
        split2(st.xv[j], st.xv[j + 1], h, l);     // pack {k, k+1}
        const uint32_t off = (uint32_t)n * (XS_STRIDE * 2) + (k8 + j) * 2;
        *(uint32_t*)(buf + OFF_XH + off) = h;
        *(uint32_t*)(buf + OFF_XL + off) = l;
    }
}

__device__ __forceinline__ void compute_chunk(float acc[2][4][4], const char* bufp,
                                              uint32_t bufa, int warp_m, int warp_n,
                                              int lane) {
    #pragma unroll
    for (int k16 = 0; k16 < 2; k16++) {
        const int k0 = k16 * 16;
        uint32_t ah[2][4], al[2][4];
        #pragma unroll
        for (int mi = 0; mi < 2; mi++) {
            const uint32_t row = warp_m + mi * 16 + (lane & 15);
            const uint32_t addr = bufa + OFF_AH + row * (AS_STRIDE * 2)
                                + (k0 + (lane >> 4) * 8) * 2;
            ldmatrix_x4(ah[mi], addr);
            ldmatrix_x4(al[mi], addr + (OFF_AL - OFF_AH));
        }
        // B frags via scalar LDS, matching m16n8k16 B map: reg j = {k,k+1} packed,
        // thread t -> n = t/4, k = k0 + 2*(t%4) (+8 for reg 1)
        uint32_t bh[4][2], bl[4][2];
        #pragma unroll
        for (int nf = 0; nf < 4; nf++) {
            const int n = warp_n + nf * 8 + (lane >> 2);
            const uint32_t boff = (uint32_t)n * (XS_STRIDE * 2) + (k0 + 2 * (lane & 3)) * 2;
            bh[nf][0] = *(const uint32_t*)(bufp + OFF_XH + boff);        // k, k+1
            bh[nf][1] = *(const uint32_t*)(bufp + OFF_XH + boff + 16);   // k+8, k+9
            bl[nf][0] = *(const uint32_t*)(bufp + OFF_XL + boff);
            bl[nf][1] = *(const uint32_t*)(bufp + OFF_XL + boff + 16);
        }
        #pragma unroll
        for (int mi = 0; mi < 2; mi++)
            #pragma unroll
            for (int nf = 0; nf < 4; nf++) {
                mma_bf16(acc[mi][nf], ah[mi], bh[nf]);
                mma_bf16(acc[mi][nf], al[mi], bh[nf]);
                mma_bf16(acc[mi][nf], ah[mi], bl[nf]);
            }
    }
}

__global__ __launch_bounds__(256) void hop_gemm_mma(const float* __restrict__ adj,
                                                    const float* __restrict__ xin,
                                                    int h) {
    extern __shared__ char smem[];
    const uint32_t smem_base = smem_u32(smem);
    const int tid = threadIdx.x;
    const int lane = tid & 31;
    const int wid = tid >> 5;
    const int warp_m = (wid & 3) * 32;    // 4 warps over M
    const int warp_n = (wid >> 2) * 32;   // 2 warps over N

    const int z = blockIdx.y;             // s*16 + b
    const int s = z >> 4;
    const int b = z & 15;
    const int m0 = blockIdx.x * 128;

    const float* A = adj + (size_t)z * (N_NODES * N_NODES);
    const float* X = (h == 0)
        ? (xin + (size_t)b * (N_NODES * C_DIM))
        : (g_hop + ((size_t)(2 * s) * B_DIM + b) * (N_NODES * C_DIM));
    float* Y = g_hop + ((size_t)(2 * s + h) * B_DIM + b) * (N_NODES * C_DIM);

    float acc[2][4][4];
    #pragma unroll
    for (int mi = 0; mi < 2; mi++)
        #pragma unroll
        for (int nf = 0; nf < 4; nf++)
            #pragma unroll
            for (int e = 0; e < 4; e++) acc[mi][nf][e] = 0.f;

    Stage st;
    ldg_chunk(st, A, X, m0, 0, tid);
    sts_chunk(st, smem, tid);
    __syncthreads();

    for (int kt = 0; kt < HOP_NCHUNK; kt++) {
        const int bf = kt & 1;
        if (kt + 1 < HOP_NCHUNK)
            ldg_chunk(st, A, X, m0, (kt + 1) * HOP_BK, tid);   // overlap with MMA
        compute_chunk(acc, smem + bf * BUF_BYTES, smem_base + bf * BUF_BYTES,
                      warp_m, warp_n, lane);
        __syncthreads();
        if (kt + 1 < HOP_NCHUNK)
            sts_chunk(st, smem + ((kt + 1) & 1) * BUF_BYTES, tid);
        __syncthreads();
    }

    // Epilogue: c-frag -> Y  (c0,c1: row=lane/4, cols 2*(lane%4)+{0,1}; c2,c3: row+8)
    const int r_base = m0 + warp_m + (lane >> 2);
    const int c_base = warp_n + 2 * (lane & 3);
    #pragma unroll
    for (int mi = 0; mi < 2; mi++)
        #pragma unroll
        for (int nf = 0; nf < 4; nf++) {
            const int row = r_base + mi * 16;
            const int col = c_base + nf * 8;
            *(float2*)(Y + (size_t)row * C_DIM + col) =
                make_float2(acc[mi][nf][0], acc[mi][nf][1]);
            *(float2*)(Y + (size_t)(row + 8) * C_DIM + col) =
                make_float2(acc[mi][nf][2], acc[mi][nf][3]);
        }
}

// ---------------------------------------------------------------------------
// Fused epilogue: out[b,n,o] = sum_ki x_g[b,n,ki] * (sum_d e[n,d]*wpool[d,ki,o])
//                             + (e[n] @ bias_pool)[o]
// Eliminates materializing W (saves 84MB write + 84MB read + ~840MB L2 reads
// of wpool; wpool is now read ~512x819KB = 105MB from L2 total).
// Grid 512 x 128 threads: thread = (node, o), 16 batch accumulators.
// ---------------------------------------------------------------------------
__global__ __launch_bounds__(128) void fused_out(const float* __restrict__ xin,
                                                 const float* __restrict__ emb,
                                                 const float* __restrict__ wpool,
                                                 const float* __restrict__ bpool,
                                                 float* __restrict__ out) {
    const int t  = threadIdx.x;
    const int o  = t & 63;
    const int nl = t >> 6;                         // 0..1
    const int n  = blockIdx.x * 2 + nl;

    float e[D_DIM];
    #pragma unroll
    for (int d = 0; d < D_DIM; d++) e[d] = emb[n * D_DIM + d];

    // x_g source base per k-term; batch stride is N*C for all of them
    const float* bases[K_TERMS];
    bases[0] = xin + (size_t)n * C_DIM;
    #pragma unroll
    for (int k = 1; k < K_TERMS; k++)
        bases[k] = g_hop + (size_t)(k - 1) * B_DIM * N_NODES * C_DIM + (size_t)n * C_DIM;

    float acc[B_DIM];
    #pragma unroll
    for (int b = 0; b < B_DIM; b++) acc[b] = 0.f;

    #pragma unroll
    for (int k = 0; k < K_TERMS; k++) {
        const float* bk = bases[k];
        for (int i4 = 0; i4 < C_DIM; i4 += 4) {
            // w[j] = sum_d e[d] * wpool[d][k*64 + i4 + j][o], j=0..3 (coalesced over o)
            float w0 = 0.f, w1 = 0.f, w2 = 0.f, w3 = 0.f;
            #pragma unroll
            for (int d = 0; d < D_DIM; d++) {
                const float* wr = wpool + (((size_t)d * KC) + k * C_DIM + i4) * O_DIM + o;
                w0 = fmaf(e[d], wr[0], w0);
                w1 = fmaf(e[d], wr[O_DIM], w1);
                w2 = fmaf(e[d], wr[2 * O_DIM], w2);
                w3 = fmaf(e[d], wr[3 * O_DIM], w3);
            }
            #pragma unroll
            for (int b = 0; b < B_DIM; b++) {
                const float4 xf = *(const float4*)(bk + (size_t)b * (N_NODES * C_DIM) + i4);
                acc[b] = fmaf(xf.x, w0, fmaf(xf.y, w1, fmaf(xf.z, w2, fmaf(xf.w, w3, acc[b]))));
            }
        }
    }

    float bias = 0.f;
    #pragma unroll
    for (int d = 0; d < D_DIM; d++)
        bias = fmaf(e[d], bpool[d * O_DIM + o], bias);

    #pragma unroll
    for (int b = 0; b < B_DIM; b++)
        out[((size_t)b * N_NODES + n) * O_DIM + o] = acc[b] + bias;
}

// ---------------------------------------------------------------------------
extern "C" void kernel_launch(void* const* d_in, const int* in_sizes, int n_in,
                              void* d_out, int out_size) {
    const float* x     = (const float*)d_in[0];  // [16,1024,64]
    const float* adj   = (const float*)d_in[1];  // [2,16,1024,1024]
    const float* emb   = (const float*)d_in[2];  // [1024,10]
    const float* wpool = (const float*)d_in[3];  // [10,5,64,64]
    const float* bpool = (const float*)d_in[4];  // [10,64]
    float* out = (float*)d_out;                  // [16,1024,64]

    static int smem_set = 0;
    if (!smem_set) {
        cudaFuncSetAttribute(hop_gemm_mma, cudaFuncAttributeMaxDynamicSharedMemorySize,
                             HOP_SMEM);
        smem_set = 1;
    }

    const dim3 ggemm(N_NODES / 128, 32, 1);               // 8 M-tiles x 32 matrices
    hop_gemm_mma<<<ggemm, 256, HOP_SMEM>>>(adj, x, 0);    // hop1 (both supports)
    hop_gemm_mma<<<ggemm, 256, HOP_SMEM>>>(adj, x, 1);    // hop2 (reads hop1)
    fused_out<<<N_NODES / 2, 128>>>(x, emb, wpool, bpool, out);
}

// round 13
// speedup vs baseline: 2.0978x; 1.8952x over previous
#include <cuda_runtime.h>
#include <cuda_bf16.h>
#include <cstdint>

// Shapes (fixed by the problem)
#define B_DIM 16
#define N_NODES 1024
#define C_DIM 64
#define O_DIM 64
#define D_DIM 10
#define K_TERMS 5              // 1 + 2*CHEB_K
#define KC (K_TERMS * C_DIM)   // 320

// Scratch (allocation-free rule: __device__ globals)
// g_hop slabs: 0=s0h1, 1=s0h2, 2=s1h1, 3=s1h2 ; layout [slab][b][n][c], fp32
__device__ float g_hop[(size_t)4 * B_DIM * N_NODES * C_DIM];     // 16.8 MB

// ---------------------------------------------------------------------------
// Helpers
// ---------------------------------------------------------------------------
__device__ __forceinline__ uint32_t smem_u32(const void* p) {
    uint32_t a;
    asm("{ .reg .u64 t; cvta.to.shared.u64 t, %1; cvt.u32.u64 %0, t; }" : "=r"(a) : "l"(p));
    return a;
}

// hi/lo bf16 split of two fp32 values, packed bf16x2 (low half = first elem)
__device__ __forceinline__ void split2(float v0, float v1, uint32_t& hi, uint32_t& lo) {
    asm("cvt.rn.bf16x2.f32 %0, %1, %2;" : "=r"(hi) : "f"(v1), "f"(v0));
    float r0 = v0 - __uint_as_float(hi << 16);
    float r1 = v1 - __uint_as_float(hi & 0xFFFF0000u);
    asm("cvt.rn.bf16x2.f32 %0, %1, %2;" : "=r"(lo) : "f"(r1), "f"(r0));
}

__device__ __forceinline__ void ldmatrix_x4(uint32_t* r, uint32_t addr) {
    asm volatile("ldmatrix.sync.aligned.m8n8.x4.shared.b16 {%0,%1,%2,%3}, [%4];"
                 : "=r"(r[0]), "=r"(r[1]), "=r"(r[2]), "=r"(r[3]) : "r"(addr));
}

__device__ __forceinline__ void mma_bf16(float* c, const uint32_t* a, const uint32_t* b) {
    asm volatile(
        "mma.sync.aligned.m16n8k16.row.col.f32.bf16.bf16.f32 "
        "{%0,%1,%2,%3}, {%4,%5,%6,%7}, {%8,%9}, {%0,%1,%2,%3};"
        : "+f"(c[0]), "+f"(c[1]), "+f"(c[2]), "+f"(c[3])
        : "r"(a[0]), "r"(a[1]), "r"(a[2]), "r"(a[3]), "r"(b[0]), "r"(b[1]));
}

// ---------------------------------------------------------------------------
// Hop GEMM via warp-level bf16 mma.sync (legacy HMMA path; tcgen05 is
// ptxas-gated to sm_103a which this harness does not target).
// Y[1024,64] = A[1024,1024] @ X[1024,64] for 32 (support,batch) matrices.
// fp32 accuracy via bf16 hi/lo split: Ah*Xh + Al*Xh + Ah*Xl.
// CTA: 256 thr / 8 warps, tile M=128 N=64, BK=32, double-buffered SMEM.
// ---------------------------------------------------------------------------
#define HOP_BK 32
#define HOP_NCHUNK (N_NODES / HOP_BK)   // 32
#define AS_STRIDE 40                    // bf16/row (80B: 16B-aligned, ldmatrix conflict-free)
#define XS_STRIDE 34                    // bf16/row (68B: odd bank stride, STS conflict-free)
#define AS_BYTES (128 * AS_STRIDE * 2)  // 10240
#define XS_BYTES (64 * XS_STRIDE * 2)   // 4352
#define OFF_AH 0
#define OFF_AL AS_BYTES
#define OFF_XH (2 * AS_BYTES)
#define OFF_XL (2 * AS_BYTES + XS_BYTES)
#define BUF_BYTES (2 * AS_BYTES + 2 * XS_BYTES)  // 29184
#define HOP_SMEM (2 * BUF_BYTES)                 // 58368

struct Stage {
    float4 a[4];
    float  xv[8];
};

__device__ __forceinline__ void ldg_chunk(Stage& st, const float* __restrict__ A,
                                          const float* __restrict__ X,
                                          int m0, int k0, int tid) {
    #pragma unroll
    for (int q = 0; q < 4; q++) {
        const int f = tid + 256 * q;          // float4 slot 0..1023
        const int m = f >> 3, kq = f & 7;     // 8 float4 per 32-wide row
        st.a[q] = *(const float4*)(A + (size_t)(m0 + m) * N_NODES + k0 + kq * 4);
    }
    const int n = tid & 63, k8 = (tid >> 6) * 8;
    #pragma unroll
    for (int j = 0; j < 8; j++)
        st.xv[j] = X[(size_t)(k0 + k8 + j) * C_DIM + n];   // coalesced along n
}

__device__ __forceinline__ void sts_chunk(const Stage& st, char* buf, int tid) {
    #pragma unroll
    for (int q = 0; q < 4; q++) {
        const int f = tid + 256 * q;
        const int m = f >> 3, kq = f & 7;
        uint32_t h0, l0, h1, l1;
        split2(st.a[q].x, st.a[q].y, h0, l0);
        split2(st.a[q].z, st.a[q].w, h1, l1);
        const uint32_t off = (uint32_t)m * (AS_STRIDE * 2) + kq * 8;
        *(uint2*)(buf + OFF_AH + off) = make_uint2(h0, h1);
        *(uint2*)(buf + OFF_AL + off) = make_uint2(l0, l1);
    }
    const int n = tid & 63, k8 = (tid >> 6) * 8;
    #pragma unroll
    for (int j = 0; j < 8; j += 2) {
        uint32_t h, l;
        split2(st.xv[j], st.xv[j + 1], h, l);     // pack {k, k+1}
        const uint32_t off = (uint32_t)n * (XS_STRIDE * 2) + (k8 + j) * 2;
        *(uint32_t*)(buf + OFF_XH + off) = h;
        *(uint32_t*)(buf + OFF_XL + off) = l;
    }
}

__device__ __forceinline__ void compute_chunk(float acc[2][4][4], const char* bufp,
                                              uint32_t bufa, int warp_m, int warp_n,
                                              int lane) {
    #pragma unroll
    for (int k16 = 0; k16 < 2; k16++) {
        const int k0 = k16 * 16;
        uint32_t ah[2][4], al[2][4];
        #pragma unroll
        for (int mi = 0; mi < 2; mi++) {
            const uint32_t row = warp_m + mi * 16 + (lane & 15);
            const uint32_t addr = bufa + OFF_AH + row * (AS_STRIDE * 2)
                                + (k0 + (lane >> 4) * 8) * 2;
            ldmatrix_x4(ah[mi], addr);
            ldmatrix_x4(al[mi], addr + (OFF_AL - OFF_AH));
        }
        // B frags via scalar LDS, matching m16n8k16 B map: reg j = {k,k+1} packed,
        // thread t -> n = t/4, k = k0 + 2*(t%4) (+8 for reg 1)
        uint32_t bh[4][2], bl[4][2];
        #pragma unroll
        for (int nf = 0; nf < 4; nf++) {
            const int n = warp_n + nf * 8 + (lane >> 2);
            const uint32_t boff = (uint32_t)n * (XS_STRIDE * 2) + (k0 + 2 * (lane & 3)) * 2;
            bh[nf][0] = *(const uint32_t*)(bufp + OFF_XH + boff);        // k, k+1
            bh[nf][1] = *(const uint32_t*)(bufp + OFF_XH + boff + 16);   // k+8, k+9
            bl[nf][0] = *(const uint32_t*)(bufp + OFF_XL + boff);
            bl[nf][1] = *(const uint32_t*)(bufp + OFF_XL + boff + 16);
        }
        #pragma unroll
        for (int mi = 0; mi < 2; mi++)
            #pragma unroll
            for (int nf = 0; nf < 4; nf++) {
                mma_bf16(acc[mi][nf], ah[mi], bh[nf]);
                mma_bf16(acc[mi][nf], al[mi], bh[nf]);
                mma_bf16(acc[mi][nf], ah[mi], bl[nf]);
            }
    }
}

__global__ __launch_bounds__(256) void hop_gemm_mma(const float* __restrict__ adj,
                                                    const float* __restrict__ xin,
                                                    int h) {
    extern __shared__ char smem[];
    const uint32_t smem_base = smem_u32(smem);
    const int tid = threadIdx.x;
    const int lane = tid & 31;
    const int wid = tid >> 5;
    const int warp_m = (wid & 3) * 32;    // 4 warps over M
    const int warp_n = (wid >> 2) * 32;   // 2 warps over N

    const int z = blockIdx.y;             // s*16 + b
    const int s = z >> 4;
    const int b = z & 15;
    const int m0 = blockIdx.x * 128;

    const float* A = adj + (size_t)z * (N_NODES * N_NODES);
    const float* X = (h == 0)
        ? (xin + (size_t)b * (N_NODES * C_DIM))
        : (g_hop + ((size_t)(2 * s) * B_DIM + b) * (N_NODES * C_DIM));
    float* Y = g_hop + ((size_t)(2 * s + h) * B_DIM + b) * (N_NODES * C_DIM);

    float acc[2][4][4];
    #pragma unroll
    for (int mi = 0; mi < 2; mi++)
        #pragma unroll
        for (int nf = 0; nf < 4; nf++)
            #pragma unroll
            for (int e = 0; e < 4; e++) acc[mi][nf][e] = 0.f;

    Stage st;
    ldg_chunk(st, A, X, m0, 0, tid);
    sts_chunk(st, smem, tid);
    __syncthreads();

    for (int kt = 0; kt < HOP_NCHUNK; kt++) {
        const int bf = kt & 1;
        if (kt + 1 < HOP_NCHUNK)
            ldg_chunk(st, A, X, m0, (kt + 1) * HOP_BK, tid);   // overlap with MMA
        compute_chunk(acc, smem + bf * BUF_BYTES, smem_base + bf * BUF_BYTES,
                      warp_m, warp_n, lane);
        __syncthreads();
        if (kt + 1 < HOP_NCHUNK)
            sts_chunk(st, smem + ((kt + 1) & 1) * BUF_BYTES, tid);
        __syncthreads();
    }

    // Epilogue: c-frag -> Y  (c0,c1: row=lane/4, cols 2*(lane%4)+{0,1}; c2,c3: row+8)
    const int r_base = m0 + warp_m + (lane >> 2);
    const int c_base = warp_n + 2 * (lane & 3);
    #pragma unroll
    for (int mi = 0; mi < 2; mi++)
        #pragma unroll
        for (int nf = 0; nf < 4; nf++) {
            const int row = r_base + mi * 16;
            const int col = c_base + nf * 8;
            *(float2*)(Y + (size_t)row * C_DIM + col) =
                make_float2(acc[mi][nf][0], acc[mi][nf][1]);
            *(float2*)(Y + (size_t)(row + 8) * C_DIM + col) =
                make_float2(acc[mi][nf][2], acc[mi][nf][3]);
        }
}

// ---------------------------------------------------------------------------
// Fused epilogue, SMEM-staged (fixes R8's 64x redundant x_g reads):
//   out[b,n,o] = sum_ki x_g[b,n,ki] * (sum_d e[n,d]*wpool[d,ki,o]) + e[n]@bpool
// CTA = 4 nodes, 256 threads, k-term loop with 3 phases:
//   A: stage x_g chunk [4n][16b][64c] to SMEM (x_g read exactly once)
//   B: compute Wk [4n][64c][64o] in SMEM from wpool (210MB L2 total, 256 CTAs)
//   C: register-tiled contraction, thread = (node, 4b x 4o)
// ---------------------------------------------------------------------------
#define EP_G 4          // nodes per CTA
#define EP_PAD 68       // row pad (floats): 16B-aligned float4, <=2-way conflicts

__global__ __launch_bounds__(256) void fused_out(const float* __restrict__ xin,
                                                 const float* __restrict__ emb,
                                                 const float* __restrict__ wpool,
                                                 const float* __restrict__ bpool,
                                                 float* __restrict__ out) {
    __shared__ float xg[EP_G][B_DIM][EP_PAD];   // 17408 B
    __shared__ float wk[EP_G][C_DIM][EP_PAD];   // 69632 B

    const int t  = threadIdx.x;
    const int n0 = blockIdx.x * EP_G;

    // Phase-C roles: thread = (nn_c, 4 o, 4 b)
    const int bg   = t & 3;            // b = bg*4 + bi
    const int og   = (t >> 2) & 15;    // o = og*4 + oi
    const int nn_c = t >> 6;           // 0..3
    // Phase-B roles
    const int o2 = t & 31;             // o pair: o = 2*o2, 2*o2+1
    const int cg = t >> 5;             // c = cg*8 + i

    // Node embeddings in registers (shared across phases)
    float ev[EP_G][D_DIM];
    #pragma unroll
    for (int nn = 0; nn < EP_G; nn++)
        #pragma unroll
        for (int d = 0; d < D_DIM; d++)
            ev[nn][d] = emb[(n0 + nn) * D_DIM + d];

    float acc[4][4];
    #pragma unroll
    for (int bi = 0; bi < 4; bi++)
        #pragma unroll
        for (int oi = 0; oi < 4; oi++) acc[bi][oi] = 0.f;

    for (int k = 0; k < K_TERMS; k++) {
        // ---- Phase A: stage x_g[k] for 4 nodes, 16 batches, 64 c ----
        const float* src = (k == 0)
            ? xin
            : g_hop + (size_t)(k - 1) * B_DIM * N_NODES * C_DIM;
        #pragma unroll
        for (int q = 0; q < 4; q++) {
            const int id = t + 256 * q;         // 0..1023 float4 slots
            const int nn = id >> 8;
            const int b  = (id >> 4) & 15;
            const int c4 = id & 15;
            const float4 v = *(const float4*)(src + (size_t)b * (N_NODES * C_DIM)
                                              + (size_t)(n0 + nn) * C_DIM + c4 * 4);
            *(float4*)&xg[nn][b][c4 * 4] = v;
        }

        // ---- Phase B: Wk[nn][c][o] = sum_d ev[nn][d] * wpool[d][k*64+c][o] ----
        #pragma unroll
        for (int i = 0; i < 8; i++) {
            const int c = cg * 8 + i;
            const int row = k * C_DIM + c;      // within KC
            float2 w[EP_G];
            #pragma unroll
            for (int nn = 0; nn < EP_G; nn++) w[nn] = make_float2(0.f, 0.f);
            #pragma unroll
            for (int d = 0; d < D_DIM; d++) {
                const float2 wv = *(const float2*)(wpool
                    + ((size_t)d * KC + row) * O_DIM + o2 * 2);
                #pragma unroll
                for (int nn = 0; nn < EP_G; nn++) {
                    w[nn].x = fmaf(ev[nn][d], wv.x, w[nn].x);
                    w[nn].y = fmaf(ev[nn][d], wv.y, w[nn].y);
                }
            }
            #pragma unroll
            for (int nn = 0; nn < EP_G; nn++)
                *(float2*)&wk[nn][c][o2 * 2] = w[nn];
        }
        __syncthreads();

        // ---- Phase C: acc[bi][oi] += sum_c xg[nn][b][c] * wk[nn][c][o] ----
        #pragma unroll 4
        for (int c4 = 0; c4 < 16; c4++) {
            float4 wo[4];
            #pragma unroll
            for (int j = 0; j < 4; j++)
                wo[j] = *(const float4*)&wk[nn_c][c4 * 4 + j][og * 4];
            #pragma unroll
            for (int bi = 0; bi < 4; bi++) {
                const float4 xb = *(const float4*)&xg[nn_c][bg * 4 + bi][c4 * 4];
                const float xs[4] = {xb.x, xb.y, xb.z, xb.w};
                #pragma unroll
                for (int j = 0; j < 4; j++) {
                    acc[bi][0] = fmaf(xs[j], wo[j].x, acc[bi][0]);
                    acc[bi][1] = fmaf(xs[j], wo[j].y, acc[bi][1]);
                    acc[bi][2] = fmaf(xs[j], wo[j].z, acc[bi][2]);
                    acc[bi][3] = fmaf(xs[j], wo[j].w, acc[bi][3]);
                }
            }
        }
        __syncthreads();   // before next k overwrites xg/wk
    }

    // Bias for this thread's 4 o values (node nn_c)
    float bias[4] = {0.f, 0.f, 0.f, 0.f};
    #pragma unroll
    for (int d = 0; d < D_DIM; d++) {
        const float4 bp = *(const float4*)(bpool + d * O_DIM + og * 4);
        bias[0] = fmaf(ev[nn_c][d], bp.x, bias[0]);
        bias[1] = fmaf(ev[nn_c][d], bp.y, bias[1]);
        bias[2] = fmaf(ev[nn_c][d], bp.z, bias[2]);
        bias[3] = fmaf(ev[nn_c][d], bp.w, bias[3]);
    }

    const int n = n0 + nn_c;
    #pragma unroll
    for (int bi = 0; bi < 4; bi++) {
        const int b = bg * 4 + bi;
        *(float4*)(out + ((size_t)b * N_NODES + n) * O_DIM + og * 4) =
            make_float4(acc[bi][0] + bias[0], acc[bi][1] + bias[1],
                        acc[bi][2] + bias[2], acc[bi][3] + bias[3]);
    }
}

// ---------------------------------------------------------------------------
extern "C" void kernel_launch(void* const* d_in, const int* in_sizes, int n_in,
                              void* d_out, int out_size) {
    const float* x     = (const float*)d_in[0];  // [16,1024,64]
    const float* adj   = (const float*)d_in[1];  // [2,16,1024,1024]
    const float* emb   = (const float*)d_in[2];  // [1024,10]
    const float* wpool = (const float*)d_in[3];  // [10,5,64,64]
    const float* bpool = (const float*)d_in[4];  // [10,64]
    float* out = (float*)d_out;                  // [16,1024,64]

    static int smem_set = 0;
    if (!smem_set) {
        cudaFuncSetAttribute(hop_gemm_mma, cudaFuncAttributeMaxDynamicSharedMemorySize,
                             HOP_SMEM);
        smem_set = 1;
    }

    const dim3 ggemm(N_NODES / 128, 32, 1);               // 8 M-tiles x 32 matrices
    hop_gemm_mma<<<ggemm, 256, HOP_SMEM>>>(adj, x, 0);    // hop1 (both supports)
    hop_gemm_mma<<<ggemm, 256, HOP_SMEM>>>(adj, x, 1);    // hop2 (reads hop1)
    fused_out<<<N_NODES / EP_G, 256>>>(x, emb, wpool, bpool, out);
}